// round 13
// baseline (speedup 1.0000x reference)
#include <cuda_runtime.h>

#define L     4096
#define TS    64                      // tile size
#define NPAIR 2080                    // total tile pairs (A <= B)
#define GRID  1040                    // blocks; each does 2 tile pairs
#define NTHR  128
#define SPAD  69                      // c2s row stride in floats (2-way conflict max)

__device__ double g_clash = 0.0;
__device__ double g_pair  = 0.0;
__device__ double g_cnt   = 0.0;
__device__ unsigned int g_done = 0;

__device__ __forceinline__ float fsqrt_approx(float x) {
    float r;
    asm("sqrt.approx.f32 %0, %1;" : "=f"(r) : "f"(x));
    return r;
}

__device__ __forceinline__ float warp_sum(float v) {
    v += __shfl_down_sync(0xffffffffu, v, 16);
    v += __shfl_down_sync(0xffffffffu, v, 8);
    v += __shfl_down_sync(0xffffffffu, v, 4);
    v += __shfl_down_sync(0xffffffffu, v, 2);
    v += __shfl_down_sync(0xffffffffu, v, 1);
    return v;
}

__device__ __forceinline__ void decode_pair(int k, int& A, int& B) {
    int a = (int)((129.0f - sqrtf(16641.0f - 8.0f * (float)k)) * 0.5f);
    while (64 * (a + 1) - (a + 1) * a / 2 <= k) ++a;
    while (64 * a - a * (a - 1) / 2 > k) --a;
    A = a;
    B = a + (k - (64 * a - a * (a - 1) / 2));
}

// Sweep an 8x4 subtile. DIAG masks to j > i inside the diagonal tile.
// IDENTICAL fp expressions/order to the R12 kernel (verified rel_err path).
template <bool DIAG>
__device__ __forceinline__ void sweep(
    int ib, int jb, int ti, int tj,
    const float4* __restrict__ c1, const float4* __restrict__ pj,
    const float4* sA4, const float* c2s,
    float& oclash, float& opair, float& ocnt)
{
    float cl0 = 0.0f, cl1 = 0.0f;       // split accumulator chains (b parity)
    float pa0 = 0.0f, pa1 = 0.0f;
    float cn0 = 0.0f, cn1 = 0.0f;
#pragma unroll
    for (int a = 0; a < 8; ++a) {
        const float4 pi = sA4[ti * 8 + a];          // broadcast LDS.128
        const float c1v[4] = {c1[a].x, c1[a].y, c1[a].z, c1[a].w};
#pragma unroll
        for (int b = 0; b < 4; ++b) {
            float cv2 = c2s[(tj * 4 + b) * SPAD + ti * 8 + a];
            float dx = pj[b].x - pi.x;
            float dy = pj[b].y - pi.y;
            float dz = pj[b].z - pi.z;
            float d2 = fmaf(dz, dz, fmaf(dy, dy, dx * dx));
            float d  = fsqrt_approx(d2);
            float t  = fmaxf(3.4f - d, 0.0f);
            float s  = c1v[b] + cv2;                // cv_ij + cv_ji
            if (DIAG) {
                float mask = (jb + b > ib + a) ? 1.0f : 0.0f;
                t *= mask;
                s *= mask;
            }
            float u = d - 9.0f;                     // target = 6.0 * 1.5
            float w = u * s;
            if (b & 1) { cl1 = fmaf(t, t, cl1); pa1 = fmaf(w, u, pa1); cn1 += s; }
            else       { cl0 = fmaf(t, t, cl0); pa0 = fmaf(w, u, pa0); cn0 += s; }
        }
    }
    oclash += cl0 + cl1;
    opair  += pa0 + pa1;
    ocnt   += cn0 + cn1;
}

// diag-tile extras: count c_ii entries + remove band pairs (j-i in {1,2}).
// Same fp expressions as R12 -> exact cancellation of swept band terms.
__device__ __forceinline__ void diag_fix(
    const float* __restrict__ coords, const float* __restrict__ cmap,
    int i0, int tid, float& aclash, float& apair, float& acnt)
{
    if (tid < TS)
        acnt += __ldg(cmap + (size_t)(i0 + tid) * L + (i0 + tid));
    const int o = 1 + (tid >> 6);            // 1 or 2
    const int i = i0 + (tid & 63);
    const int j = i + o;
    if (j < L) {
        float xi = __ldg(coords + 3 * i + 0);
        float yi = __ldg(coords + 3 * i + 1);
        float zi = __ldg(coords + 3 * i + 2);
        float xJ = __ldg(coords + 3 * j + 0);
        float yJ = __ldg(coords + 3 * j + 1);
        float zJ = __ldg(coords + 3 * j + 2);
        float dx = xJ - xi, dy = yJ - yi, dz = zJ - zi;
        float d2 = fmaf(dz, dz, fmaf(dy, dy, dx * dx));
        float d  = fsqrt_approx(d2);
        float t  = fmaxf(3.4f - d, 0.0f);
        aclash   = fmaf(-t, t, aclash);
        float s  = __ldg(cmap + (size_t)i * L + j) + __ldg(cmap + (size_t)j * L + i);
        float u  = d - 9.0f;
        float w  = u * s;
        apair    = fmaf(-w, u, apair);
        // band contacts remain in acnt (reference counts them in n_pairs)
    }
}

__global__ void __launch_bounds__(NTHR, 4)
energy_kernel(const float* __restrict__ coords,
              const float* __restrict__ cmap,
              float* __restrict__ out)
{
    __shared__ float4 sA4[2][TS], sB4[2][TS];    // {x,y,z,0} per residue per iter
    __shared__ float  c2s[2][TS * SPAD];         // double-buffered C2 tiles
    __shared__ float  red[16];

    const int tid = threadIdx.x;
    int A0, B0, A1, B1;
    decode_pair((int)blockIdx.x,        A0, B0);
    decode_pair((int)blockIdx.x + GRID, A1, B1);
    const int i00 = A0 * TS, j00 = B0 * TS;
    const int i01 = A1 * TS, j01 = B1 * TS;

    // coords staging for both iterations (64 threads each)
    {
        const int it = tid >> 6;
        const int t  = tid & 63;
        const int ia = (it ? i01 : i00) + t;
        const int jb = (it ? j01 : j00) + t;
        sA4[it][t] = make_float4(__ldg(coords + 3 * ia + 0),
                                 __ldg(coords + 3 * ia + 1),
                                 __ldg(coords + 3 * ia + 2), 0.0f);
        sB4[it][t] = make_float4(__ldg(coords + 3 * jb + 0),
                                 __ldg(coords + 3 * jb + 1),
                                 __ldg(coords + 3 * jb + 2), 0.0f);
    }

    const int ti = tid >> 4;                     // 0..7  -> 8 i-rows
    const int tj = tid & 15;                     // 0..15 -> 4 j-cols
    const int ib0 = i00 + ti * 8, jb0 = j00 + tj * 4;
    const int ib1 = i01 + ti * 8, jb1 = j01 + tj * 4;

    // ---- front-load: c2-0, c1-0, c2-1 (24 LDG.128 in flight) ----
    float4 t2a[8], c1a[8], t2b[8];
#pragma unroll
    for (int m = 0; m < 8; ++m) {
        const int s = tid + m * NTHR;
        t2a[m] = __ldg(((const float4*)(cmap + (size_t)(j00 + (s >> 4)) * L + i00)) + (s & 15));
    }
#pragma unroll
    for (int r = 0; r < 8; ++r)
        c1a[r] = __ldg(((const float4*)(cmap + (size_t)(ib0 + r) * L + j00)) + tj);
#pragma unroll
    for (int m = 0; m < 8; ++m) {
        const int s = tid + m * NTHR;
        t2b[m] = __ldg(((const float4*)(cmap + (size_t)(j01 + (s >> 4)) * L + i01)) + (s & 15));
    }

    // stage c2-0 into smem buffer 0
#pragma unroll
    for (int m = 0; m < 8; ++m) {
        const int s = tid + m * NTHR;
        float* dst = &c2s[0][(s >> 4) * SPAD + (s & 15) * 4];
        dst[0] = t2a[m].x; dst[1] = t2a[m].y; dst[2] = t2a[m].z; dst[3] = t2a[m].w;
    }
    __syncthreads();

    float aclash = 0.0f, apair = 0.0f, acnt = 0.0f;

    // ---- iteration 0 (t2b stays resident in registers) ----
    {
        float4 pj[4];
#pragma unroll
        for (int b = 0; b < 4; ++b) pj[b] = sB4[0][tj * 4 + b];
        if (A0 == B0) {
            sweep<true >(ib0, jb0, ti, tj, c1a, pj, sA4[0], c2s[0], aclash, apair, acnt);
            diag_fix(coords, cmap, i00, tid, aclash, apair, acnt);
        } else {
            sweep<false>(ib0, jb0, ti, tj, c1a, pj, sA4[0], c2s[0], aclash, apair, acnt);
        }
    }

    // stage c2-1, then issue c1-1 loads (latency hidden by STS/barrier/other warps)
#pragma unroll
    for (int m = 0; m < 8; ++m) {
        const int s = tid + m * NTHR;
        float* dst = &c2s[1][(s >> 4) * SPAD + (s & 15) * 4];
        dst[0] = t2b[m].x; dst[1] = t2b[m].y; dst[2] = t2b[m].z; dst[3] = t2b[m].w;
    }
    float4 c1b[8];
#pragma unroll
    for (int r = 0; r < 8; ++r)
        c1b[r] = __ldg(((const float4*)(cmap + (size_t)(ib1 + r) * L + j01)) + tj);
    __syncthreads();

    // ---- iteration 1 ----
    {
        float4 pj[4];
#pragma unroll
        for (int b = 0; b < 4; ++b) pj[b] = sB4[1][tj * 4 + b];
        if (A1 == B1) {
            sweep<true >(ib1, jb1, ti, tj, c1b, pj, sA4[1], c2s[1], aclash, apair, acnt);
            diag_fix(coords, cmap, i01, tid, aclash, apair, acnt);
        } else {
            sweep<false>(ib1, jb1, ti, tj, c1b, pj, sA4[1], c2s[1], aclash, apair, acnt);
        }
    }

    // ---- block reduction (4 warps) ----
    aclash = warp_sum(aclash);
    apair  = warp_sum(apair);
    acnt   = warp_sum(acnt);
    const int wid  = tid >> 5;
    const int lane = tid & 31;
    if (lane == 0) {
        red[wid]     = aclash;
        red[4 + wid] = apair;
        red[8 + wid] = acnt;
    }
    __syncthreads();
    if (tid == 0) {
        float cs = 0.0f, ps = 0.0f, ns = 0.0f;
        for (int w = 0; w < 4; ++w) { cs += red[w]; ps += red[4 + w]; ns += red[8 + w]; }
        atomicAdd(&g_clash, (double)cs);
        atomicAdd(&g_pair,  (double)ps);
        atomicAdd(&g_cnt,   (double)ns);
        __threadfence();
        unsigned prev = atomicAdd(&g_done, 1u);
        red[12] = (prev == (unsigned)(GRID - 1)) ? 1.0f : 0.0f;
    }
    __syncthreads();

    // last block: bond term + finalize + reset for next graph replay
    if (red[12] != 0.0f) {
        float b = 0.0f;
        for (int k2 = tid; k2 < L - 1; k2 += NTHR) {
            float dx = __ldg(coords + 3 * k2 + 3) - __ldg(coords + 3 * k2 + 0);
            float dy = __ldg(coords + 3 * k2 + 4) - __ldg(coords + 3 * k2 + 1);
            float dz = __ldg(coords + 3 * k2 + 5) - __ldg(coords + 3 * k2 + 2);
            float d  = fsqrt_approx(fmaf(dz, dz, fmaf(dy, dy, dx * dx)));
            float t  = d - 6.0f;                 // IDEAL_C1_C1
            b = fmaf(t, t, b);
        }
        b = warp_sum(b);
        __syncthreads();
        if (lane == 0) red[wid] = b;
        __syncthreads();
        if (tid == 0) {
            float bs = 0.0f;
            for (int w = 0; w < 4; ++w) bs += red[w];
            double e_bond  = (double)bs / (double)(L - 1);
            double e_clash = g_clash / (double)L;   // unordered j>=i+3, counted once
            double cnt     = g_cnt < 1.0 ? 1.0 : g_cnt;
            double e_pair  = g_pair / cnt;
            out[0] = (float)(e_bond + 2.0 * e_clash + 0.5 * e_pair);
            g_clash = 0.0;
            g_pair  = 0.0;
            g_cnt   = 0.0;
            g_done  = 0u;
        }
    }
}

extern "C" void kernel_launch(void* const* d_in, const int* in_sizes, int n_in,
                              void* d_out, int out_size) {
    const float* a0 = (const float*)d_in[0];
    const float* a1 = (const float*)d_in[1];
    // coords is the small input (L*3), contact_map the big one (L*L)
    const float* coords = (in_sizes[0] < in_sizes[1]) ? a0 : a1;
    const float* cmap   = (in_sizes[0] < in_sizes[1]) ? a1 : a0;
    energy_kernel<<<GRID, NTHR>>>(coords, cmap, (float*)d_out);
}